// round 7
// baseline (speedup 1.0000x reference)
#include <cuda_runtime.h>
#include <cuda_bf16.h>

// Problem constants
#define B 4
#define N 256
#define F 128
#define H 256

typedef unsigned long long ull;

// Scratch (allocation-free rule: __device__ globals)
__device__ __align__(16) float g_ub[B * H];     // u[b,h] + b1[h]
__device__ __align__(16) float g_A[B * N * H];  // relu(x_i) @ W1_i   (raw, no ub)
__device__ __align__(16) float g_C[B * N * H];  // relu(x_j) @ W1_j

// ---- packed f32x2 helpers (sm_100+) ---------------------------------------
static __device__ __forceinline__ ull add2(ull a, ull b) {
    ull d; asm("add.rn.f32x2 %0, %1, %2;" : "=l"(d) : "l"(a), "l"(b)); return d;
}
static __device__ __forceinline__ ull fma2(ull a, ull b, ull c) {
    ull d; asm("fma.rn.f32x2 %0, %1, %2, %3;" : "=l"(d) : "l"(a), "l"(b), "l"(c)); return d;
}
static __device__ __forceinline__ ull pack2(float lo, float hi) {
    ull d; asm("mov.b64 %0, {%1, %2};" : "=l"(d) : "f"(lo), "f"(hi)); return d;
}
static __device__ __forceinline__ void unpack2(ull v, float& lo, float& hi) {
    asm("mov.b64 {%0, %1}, %2;" : "=f"(lo), "=f"(hi) : "l"(v));
}
static __device__ __forceinline__ ull relu2(ull v) {
    float lo, hi; unpack2(v, lo, hi);
    return pack2(fmaxf(lo, 0.f), fmaxf(hi, 0.f));
}
static __device__ __forceinline__ float hsum2(ull v) {
    float lo, hi; unpack2(v, lo, hi); return lo + hi;
}

// ---------------------------------------------------------------------------
// Kernel 1: fused nodegemm (blocks 0..127) + pool (blocks 128..131).
//   512 threads.  Gemm blocks: (row-group of 16 rows) x (h-half of 128).
//   Each thread: 4 rows (rg = tid>>7) x 1 h (hl = tid&127), dual GEMM.
// ---------------------------------------------------------------------------
#define CF 16         // f per chunk
#define NCHUNK (F / CF)
#define HW 128        // h per gemm block

__global__ void __launch_bounds__(512) k_main(
        const float* __restrict__ x,
        const float* __restrict__ Wp,
        const float* __restrict__ W1,
        const float* __restrict__ b1) {
    __shared__ __align__(16) float rx[F * 16];             // [f][16 rows] 8 KB
    __shared__ __align__(16) float wbuf[2][CF][2][HW];     // 32 KB staged W1a/W1c
    int tid = threadIdx.x;

    if (blockIdx.x < 128) {
        // ================== nodegemm ==================
        int row0 = (blockIdx.x >> 1) * 16;     // 16 rows per block
        int h0   = (blockIdx.x & 1) * HW;      // h-half
        int hl = tid & (HW - 1);               // 0..127
        int rg = tid >> 7;                     // 0..3 -> rows rg*4..rg*4+3

        // rx packed: word f*16 + r  => row-pairs contiguous (8B)
        #pragma unroll
        for (int k = 0; k < 4; k++) {
            int idx = tid + k * 512;
            int r = idx >> 7, f = idx & (F - 1);
            rx[f * 16 + r] = fmaxf(x[(row0 + r) * F + f], 0.f);
        }

        const float* W1base = W1 + (size_t)F * H + h0;  // rows [F,3F), this h-half

        // prologue: fetch chunk 0 and stage it (2 float4 per thread)
        float4 t0, t1;
        {
            #pragma unroll
            for (int k = 0; k < 2; k++) {
                int idx = tid + k * 512;            // 0..1023 float4s
                int part = idx >> 9;                // 0 = A-weights, 1 = C
                int rem = idx & 511;
                int fl = rem >> 5, q = rem & 31;
                float4 v = ((const float4*)(W1base + ((size_t)(part * F + fl)) * H))[q];
                if (k == 0) t0 = v; else t1 = v;
            }
            #pragma unroll
            for (int k = 0; k < 2; k++) {
                int idx = tid + k * 512;
                int part = idx >> 9;
                int rem = idx & 511;
                int fl = rem >> 5, q = rem & 31;
                float4 v = (k == 0) ? t0 : t1;
                ((float4*)&wbuf[0][fl][part][0])[q] = v;
            }
        }
        __syncthreads();

        const ull* rxu = (const ull*)rx;            // [F][8] row-pairs
        ull accA[2] = {0, 0};
        ull accC[2] = {0, 0};

        for (int c = 0; c < NCHUNK; c++) {
            int s = c & 1;
            bool pf = (c + 1) < NCHUNK;
            // prefetch next chunk into registers
            if (pf) {
                int fb = (c + 1) * CF;
                #pragma unroll
                for (int k = 0; k < 2; k++) {
                    int idx = tid + k * 512;
                    int part = idx >> 9;
                    int rem = idx & 511;
                    int fl = rem >> 5, q = rem & 31;
                    float4 v = ((const float4*)(W1base + ((size_t)(part * F + fb + fl)) * H))[q];
                    if (k == 0) t0 = v; else t1 = v;
                }
            }
            // compute current chunk from smem
            #pragma unroll
            for (int fl = 0; fl < CF; fl++) {
                int f = c * CF + fl;
                float wa = wbuf[s][fl][0][hl];
                float wc = wbuf[s][fl][1][hl];
                ull wa2 = pack2(wa, wa);
                ull wc2 = pack2(wc, wc);
                ull v0 = rxu[f * 8 + rg * 2 + 0];   // broadcast within rg-group
                ull v1 = rxu[f * 8 + rg * 2 + 1];
                accA[0] = fma2(v0, wa2, accA[0]);
                accA[1] = fma2(v1, wa2, accA[1]);
                accC[0] = fma2(v0, wc2, accC[0]);
                accC[1] = fma2(v1, wc2, accC[1]);
            }
            // stage prefetched chunk
            if (pf) {
                int ns = (c + 1) & 1;
                #pragma unroll
                for (int k = 0; k < 2; k++) {
                    int idx = tid + k * 512;
                    int part = idx >> 9;
                    int rem = idx & 511;
                    int fl = rem >> 5, q = rem & 31;
                    float4 v = (k == 0) ? t0 : t1;
                    ((float4*)&wbuf[ns][fl][part][0])[q] = v;
                }
            }
            __syncthreads();
        }

        #pragma unroll
        for (int p = 0; p < 2; p++) {
            int r0g = row0 + rg * 4 + 2 * p;
            float a0, a1, c0, c1;
            unpack2(accA[p], a0, a1);
            unpack2(accC[p], c0, c1);
            g_A[r0g * H + h0 + hl]       = a0;
            g_A[(r0g + 1) * H + h0 + hl] = a1;
            g_C[r0g * H + h0 + hl]       = c0;
            g_C[(r0g + 1) * H + h0 + hl] = c1;
        }
    } else {
        // ================== pool (512 threads) ==================
        int b = blockIdx.x - 128;
        float* part4 = rx;              // [4][F]  (512 floats)
        float* m     = rx + 512;        // [F]
        float* r     = rx + 640;        // [F]
        const float* xb = x + b * N * F;

        // Phase 1: column mean. 4 groups x 64 nodes, 8 indep accumulators.
        {
            int f = tid & (F - 1);
            int g = tid >> 7;                       // 0..3
            const float* base = xb + g * 64 * F + f;
            float s0 = 0.f, s1 = 0.f, s2 = 0.f, s3 = 0.f;
            float s4 = 0.f, s5 = 0.f, s6 = 0.f, s7 = 0.f;
            #pragma unroll
            for (int n = 0; n < 8; n++) {
                s0 += base[(n) * F];
                s1 += base[(n + 8) * F];
                s2 += base[(n + 16) * F];
                s3 += base[(n + 24) * F];
                s4 += base[(n + 32) * F];
                s5 += base[(n + 40) * F];
                s6 += base[(n + 48) * F];
                s7 += base[(n + 56) * F];
            }
            part4[g * F + f] = ((s0 + s1) + (s2 + s3)) + ((s4 + s5) + (s6 + s7));
        }
        __syncthreads();
        if (tid < F)
            m[tid] = (part4[tid] + part4[F + tid] + part4[2 * F + tid] + part4[3 * F + tid]) * (1.0f / N);
        __syncthreads();

        // Phase 2: hp[f] = relu(sum m[fin] * Wp[fin, f]).  4 groups x 32 fin.
        {
            int f = tid & (F - 1);
            int g = tid >> 7;
            float s0 = 0.f, s1 = 0.f, s2 = 0.f, s3 = 0.f;
            #pragma unroll
            for (int k = 0; k < 8; k++) {
                int fin = g * 32 + k;
                s0 += m[fin]      * Wp[fin * F + f];
                s1 += m[fin + 8]  * Wp[(fin + 8) * F + f];
                s2 += m[fin + 16] * Wp[(fin + 16) * F + f];
                s3 += m[fin + 24] * Wp[(fin + 24) * F + f];
            }
            part4[g * F + f] = (s0 + s1) + (s2 + s3);
        }
        __syncthreads();
        if (tid < F)
            r[tid] = fmaxf(part4[tid] + part4[F + tid] + part4[2 * F + tid] + part4[3 * F + tid], 0.f);
        __syncthreads();

        // Phase 3: u[h] = sum_f r[f] * W1[f, h] + b1[h].  2 groups x 64 f.
        {
            int h = tid & (H - 1);
            int g = tid >> 8;                       // 0..1
            float s0 = 0.f, s1 = 0.f, s2 = 0.f, s3 = 0.f;
            #pragma unroll
            for (int f = 0; f < 16; f++) {
                int fb = g * 64 + f;
                s0 += r[fb]      * W1[fb * H + h];
                s1 += r[fb + 16] * W1[(fb + 16) * H + h];
                s2 += r[fb + 32] * W1[(fb + 32) * H + h];
                s3 += r[fb + 48] * W1[(fb + 48) * H + h];
            }
            part4[g * H + h] = (s0 + s1) + (s2 + s3);
        }
        __syncthreads();
        if (tid < H)
            g_ub[b * H + tid] = part4[tid] + part4[H + tid] + b1[tid];
    }
}

// ---------------------------------------------------------------------------
// Kernel 2: pairwise fused readout.  grid(8,8,B), block(512)
//   32x32 output tile; thread (tj, ti, hh) computes 4i x 2j partials over its
//   32-h slice of each 128-h half (hh = tid>>7 in 0..3); 3-round smem
//   reduction combines the hh slices.
// ---------------------------------------------------------------------------
#define HS 128          // h per smem-resident half
#define RQ 130          // row stride in floats (130%32==2: conflict-free LDS.64)
#define RQU 65          // row stride in ull

__global__ void __launch_bounds__(512) k_pair(
        const float* __restrict__ W2,
        const float* __restrict__ b2,
        float* __restrict__ out) {
    __shared__ __align__(16) float As[32 * RQ];
    __shared__ __align__(16) float Cs[32 * RQ];
    __shared__ __align__(16) float w2s[H];
    __shared__ __align__(16) float ubs[H];
    __shared__ __align__(16) float psum[128][9];

    int b  = blockIdx.z;
    int i0 = blockIdx.y * 32;
    int j0 = blockIdx.x * 32;
    int tid = threadIdx.x;

    if (tid < 256) {
        w2s[tid] = W2[tid];
        ubs[tid] = g_ub[b * H + tid];
    }

    int tj = tid & 15;          // j-group: cols tj, tj+16
    int ti = (tid >> 4) & 7;    // i-group: rows ti, ti+8, ti+16, ti+24
    int hh = tid >> 7;          // h-slice (0..3): 32 h of each half

    ull acc00 = 0, acc01 = 0;   // row ti
    ull acc10 = 0, acc11 = 0;   // row ti+8
    ull acc20 = 0, acc21 = 0;   // row ti+16
    ull acc30 = 0, acc31 = 0;   // row ti+24

    #pragma unroll
    for (int half = 0; half < 2; half++) {
        int ho = half * HS;
        __syncthreads();        // (also covers w2s/ubs readiness on half 0)
        // ---- fill tiles (ub folded into A); 512 threads, 2+2 float4 each ----
        #pragma unroll
        for (int k = 0; k < 2; k++) {
            int idx = tid + k * 512;        // 0..1023: r = idx>>5, q = idx&31
            int r = idx >> 5, q = idx & 31;
            float4 a = ((const float4*)(g_A + ((size_t)(b * N + i0 + r)) * H + ho))[q];
            float4 u = ((const float4*)(ubs + ho))[q];
            float2* da = (float2*)(As + r * RQ + 4 * q);
            da[0] = make_float2(a.x + u.x, a.y + u.y);
            da[1] = make_float2(a.z + u.z, a.w + u.w);
            float4 c = ((const float4*)(g_C + ((size_t)(b * N + j0 + r)) * H + ho))[q];
            float2* dc = (float2*)(Cs + r * RQ + 4 * q);
            dc[0] = make_float2(c.x, c.y);
            dc[1] = make_float2(c.z, c.w);
        }
        __syncthreads();

        // ---- compute: this thread's 16 h-pairs of this half ----
        int hq = hh * 16;                    // ull offset within row
        const ull* a0p = (const ull*)As + (size_t)ti * RQU + hq;
        const ull* a1p = a0p + 8 * RQU;
        const ull* a2p = a0p + 16 * RQU;
        const ull* a3p = a0p + 24 * RQU;
        const ull* c0p = (const ull*)Cs + (size_t)tj * RQU + hq;
        const ull* c1p = c0p + 16 * RQU;
        const ull* wp  = (const ull*)(w2s + ho) + hq;

        #pragma unroll 8
        for (int q = 0; q < 16; q++) {
            ull a0 = a0p[q];
            ull a1 = a1p[q];
            ull a2 = a2p[q];
            ull a3 = a3p[q];
            ull c0 = c0p[q];
            ull c1 = c1p[q];
            ull w  = wp[q];
            acc00 = fma2(relu2(add2(a0, c0)), w, acc00);
            acc01 = fma2(relu2(add2(a0, c1)), w, acc01);
            acc10 = fma2(relu2(add2(a1, c0)), w, acc10);
            acc11 = fma2(relu2(add2(a1, c1)), w, acc11);
            acc20 = fma2(relu2(add2(a2, c0)), w, acc20);
            acc21 = fma2(relu2(add2(a2, c1)), w, acc21);
            acc30 = fma2(relu2(add2(a3, c0)), w, acc30);
            acc31 = fma2(relu2(add2(a3, c1)), w, acc31);
        }
    }

    // ---- 3-round reduction of the 4 hh slices ----
    float v0 = hsum2(acc00), v1 = hsum2(acc01);
    float v2 = hsum2(acc10), v3 = hsum2(acc11);
    float v4 = hsum2(acc20), v5 = hsum2(acc21);
    float v6 = hsum2(acc30), v7 = hsum2(acc31);

    int p = tid & 127;
    #pragma unroll
    for (int rnd = 1; rnd < 4; rnd++) {
        __syncthreads();
        if (hh == rnd) {
            psum[p][0] = v0; psum[p][1] = v1; psum[p][2] = v2; psum[p][3] = v3;
            psum[p][4] = v4; psum[p][5] = v5; psum[p][6] = v6; psum[p][7] = v7;
        }
        __syncthreads();
        if (hh == 0) {
            v0 += psum[p][0]; v1 += psum[p][1]; v2 += psum[p][2]; v3 += psum[p][3];
            v4 += psum[p][4]; v5 += psum[p][5]; v6 += psum[p][6]; v7 += psum[p][7];
        }
    }

    if (hh == 0) {
        float b2v = b2[0];
        size_t base = ((size_t)(b * N)) * N;
        size_t r0 = base + (size_t)(i0 + ti) * N + j0;
        out[r0 + tj]               = v0 + b2v;
        out[r0 + tj + 16]          = v1 + b2v;
        out[r0 + 8 * N + tj]       = v2 + b2v;
        out[r0 + 8 * N + tj + 16]  = v3 + b2v;
        out[r0 + 16 * N + tj]      = v4 + b2v;
        out[r0 + 16 * N + tj + 16] = v5 + b2v;
        out[r0 + 24 * N + tj]      = v6 + b2v;
        out[r0 + 24 * N + tj + 16] = v7 + b2v;
    }
}

// ---------------------------------------------------------------------------
extern "C" void kernel_launch(void* const* d_in, const int* in_sizes, int n_in,
                              void* d_out, int out_size) {
    const float* x   = (const float*)d_in[0];  // [B,N,F]
    const float* Wp  = (const float*)d_in[1];  // [F,F]
    const float* W1  = (const float*)d_in[2];  // [3F,H]
    const float* b1  = (const float*)d_in[3];  // [H]
    const float* W2  = (const float*)d_in[4];  // [H,1]
    const float* b2  = (const float*)d_in[5];  // [1]
    float* out = (float*)d_out;                // [B,N,N,1]

    k_main<<<132, 512>>>(x, Wp, W1, b1);
    k_pair<<<dim3(N / 32, N / 32, B), 512>>>(W2, b2, out);
}

// round 9
// speedup vs baseline: 1.3222x; 1.3222x over previous
#include <cuda_runtime.h>
#include <cuda_bf16.h>

// Problem constants
#define B 4
#define N 256
#define F 128
#define H 256

typedef unsigned long long ull;

// Scratch (allocation-free rule: __device__ globals)
__device__ __align__(16) float g_ub[B * H];     // u[b,h] + b1[h]
__device__ __align__(16) float g_A[B * N * H];  // relu(x_i) @ W1_i   (raw, no ub)
__device__ __align__(16) float g_C[B * N * H];  // relu(x_j) @ W1_j

// ---- packed f32x2 helpers (sm_100+) ---------------------------------------
static __device__ __forceinline__ ull add2(ull a, ull b) {
    ull d; asm("add.rn.f32x2 %0, %1, %2;" : "=l"(d) : "l"(a), "l"(b)); return d;
}
static __device__ __forceinline__ ull fma2(ull a, ull b, ull c) {
    ull d; asm("fma.rn.f32x2 %0, %1, %2, %3;" : "=l"(d) : "l"(a), "l"(b), "l"(c)); return d;
}
static __device__ __forceinline__ ull pack2(float lo, float hi) {
    ull d; asm("mov.b64 %0, {%1, %2};" : "=l"(d) : "f"(lo), "f"(hi)); return d;
}
static __device__ __forceinline__ void unpack2(ull v, float& lo, float& hi) {
    asm("mov.b64 {%0, %1}, %2;" : "=f"(lo), "=f"(hi) : "l"(v));
}
static __device__ __forceinline__ ull relu2(ull v) {
    float lo, hi; unpack2(v, lo, hi);
    return pack2(fmaxf(lo, 0.f), fmaxf(hi, 0.f));
}
static __device__ __forceinline__ float hsum2(ull v) {
    float lo, hi; unpack2(v, lo, hi); return lo + hi;
}

// ---------------------------------------------------------------------------
// Kernel 1 (R5 structure): fused nodegemm (blocks 0..127) + pool (128..131).
//   256 threads.  Gemm blocks: (row-group of 16 rows) x (h-half of 128).
// ---------------------------------------------------------------------------
#define CF 16         // f per chunk
#define NCHUNK (F / CF)
#define HW 128        // h per gemm block

__global__ void __launch_bounds__(256) k_main(
        const float* __restrict__ x,
        const float* __restrict__ Wp,
        const float* __restrict__ W1,
        const float* __restrict__ b1) {
    __shared__ __align__(16) float rx[F * 16];             // [f][16 rows] 8 KB
    __shared__ __align__(16) float wbuf[2][CF][2][HW];     // 32 KB staged W1a/W1c
    int tid = threadIdx.x;

    if (blockIdx.x < 128) {
        // ================== nodegemm ==================
        int row0 = (blockIdx.x >> 1) * 16;     // 16 rows per block
        int h0   = (blockIdx.x & 1) * HW;      // h-half
        int hl = tid & (HW - 1);               // 0..127
        int rg = tid >> 7;                     // 0..1 -> rows rg*8..rg*8+7

        // rx packed: word f*16 + r  => row-pairs contiguous (8B)
        #pragma unroll
        for (int k = 0; k < 8; k++) {
            int idx = tid + k * 256;
            int r = idx >> 7, f = idx & (F - 1);
            rx[f * 16 + r] = fmaxf(x[(row0 + r) * F + f], 0.f);
        }

        const float* W1base = W1 + (size_t)F * H + h0;  // rows [F,3F), this h-half

        // prologue: fetch chunk 0 and stage it
        float4 t0, t1, t2, t3;
        {
            #pragma unroll
            for (int k = 0; k < 4; k++) {
                int idx = tid + k * 256;            // 0..1023 float4s
                int part = idx >> 9;                // 0 = A-weights, 1 = C
                int rem = idx & 511;
                int fl = rem >> 5, q = rem & 31;
                float4 v = ((const float4*)(W1base + ((size_t)(part * F + fl)) * H))[q];
                if (k == 0) t0 = v; else if (k == 1) t1 = v;
                else if (k == 2) t2 = v; else t3 = v;
            }
            #pragma unroll
            for (int k = 0; k < 4; k++) {
                int idx = tid + k * 256;
                int part = idx >> 9;
                int rem = idx & 511;
                int fl = rem >> 5, q = rem & 31;
                float4 v = (k == 0) ? t0 : (k == 1) ? t1 : (k == 2) ? t2 : t3;
                ((float4*)&wbuf[0][fl][part][0])[q] = v;
            }
        }
        __syncthreads();

        const ull* rxu = (const ull*)rx;            // [F][8] row-pairs
        ull accA[4] = {0, 0, 0, 0};
        ull accC[4] = {0, 0, 0, 0};

        for (int c = 0; c < NCHUNK; c++) {
            int s = c & 1;
            bool pf = (c + 1) < NCHUNK;
            // prefetch next chunk into registers
            if (pf) {
                int fb = (c + 1) * CF;
                #pragma unroll
                for (int k = 0; k < 4; k++) {
                    int idx = tid + k * 256;
                    int part = idx >> 9;
                    int rem = idx & 511;
                    int fl = rem >> 5, q = rem & 31;
                    float4 v = ((const float4*)(W1base + ((size_t)(part * F + fb + fl)) * H))[q];
                    if (k == 0) t0 = v; else if (k == 1) t1 = v;
                    else if (k == 2) t2 = v; else t3 = v;
                }
            }
            // compute current chunk from smem
            #pragma unroll
            for (int fl = 0; fl < CF; fl++) {
                int f = c * CF + fl;
                float wa = wbuf[s][fl][0][hl];
                float wc = wbuf[s][fl][1][hl];
                ull wa2 = pack2(wa, wa);
                ull wc2 = pack2(wc, wc);
                ull v0 = rxu[f * 8 + rg * 4 + 0];   // broadcast within rg-group
                ull v1 = rxu[f * 8 + rg * 4 + 1];
                ull v2 = rxu[f * 8 + rg * 4 + 2];
                ull v3 = rxu[f * 8 + rg * 4 + 3];
                accA[0] = fma2(v0, wa2, accA[0]);
                accA[1] = fma2(v1, wa2, accA[1]);
                accA[2] = fma2(v2, wa2, accA[2]);
                accA[3] = fma2(v3, wa2, accA[3]);
                accC[0] = fma2(v0, wc2, accC[0]);
                accC[1] = fma2(v1, wc2, accC[1]);
                accC[2] = fma2(v2, wc2, accC[2]);
                accC[3] = fma2(v3, wc2, accC[3]);
            }
            // stage prefetched chunk
            if (pf) {
                int ns = (c + 1) & 1;
                #pragma unroll
                for (int k = 0; k < 4; k++) {
                    int idx = tid + k * 256;
                    int part = idx >> 9;
                    int rem = idx & 511;
                    int fl = rem >> 5, q = rem & 31;
                    float4 v = (k == 0) ? t0 : (k == 1) ? t1 : (k == 2) ? t2 : t3;
                    ((float4*)&wbuf[ns][fl][part][0])[q] = v;
                }
            }
            __syncthreads();
        }

        #pragma unroll
        for (int p = 0; p < 4; p++) {
            int r0g = row0 + rg * 8 + 2 * p;
            float a0, a1, c0, c1;
            unpack2(accA[p], a0, a1);
            unpack2(accC[p], c0, c1);
            g_A[r0g * H + h0 + hl]       = a0;
            g_A[(r0g + 1) * H + h0 + hl] = a1;
            g_C[r0g * H + h0 + hl]       = c0;
            g_C[(r0g + 1) * H + h0 + hl] = c1;
        }
    } else {
        // ================== pool ==================
        int b = blockIdx.x - 128;
        float* part2 = rx;              // [2][F]
        float* m     = rx + 256;        // [F]
        float* r     = rx + 384;        // [F]
        const float* xb = x + b * N * F;

        // Phase 1: column mean (2 groups x 128 nodes, 4 indep accumulators)
        {
            int f = tid & (F - 1);
            int g = tid >> 7;
            const float* base = xb + g * 128 * F + f;
            float s0 = 0.f, s1 = 0.f, s2 = 0.f, s3 = 0.f;
            #pragma unroll
            for (int n = 0; n < 32; n++) {
                s0 += base[(n) * F];
                s1 += base[(n + 32) * F];
                s2 += base[(n + 64) * F];
                s3 += base[(n + 96) * F];
            }
            part2[g * F + f] = (s0 + s1) + (s2 + s3);
        }
        __syncthreads();
        if (tid < F) m[tid] = (part2[tid] + part2[F + tid]) * (1.0f / N);
        __syncthreads();

        // Phase 2: hp[f] = relu(sum m[fin] * Wp[fin, f])
        {
            int f = tid & (F - 1);
            int g = tid >> 7;
            float s0 = 0.f, s1 = 0.f;
            #pragma unroll
            for (int k = 0; k < 32; k++) {
                int fin = g * 64 + k;
                s0 += m[fin] * Wp[fin * F + f];
                s1 += m[fin + 32] * Wp[(fin + 32) * F + f];
            }
            part2[g * F + f] = s0 + s1;
        }
        __syncthreads();
        if (tid < F) r[tid] = fmaxf(part2[tid] + part2[F + tid], 0.f);
        __syncthreads();

        // Phase 3: u[h] = sum_f r[f] * W1[f, h] + b1[h]
        {
            int h = tid;
            float s0 = 0.f, s1 = 0.f, s2 = 0.f, s3 = 0.f;
            #pragma unroll
            for (int f = 0; f < 32; f++) {
                s0 += r[f]      * W1[f * H + h];
                s1 += r[f + 32] * W1[(f + 32) * H + h];
                s2 += r[f + 64] * W1[(f + 64) * H + h];
                s3 += r[f + 96] * W1[(f + 96) * H + h];
            }
            g_ub[b * H + h] = (s0 + s1) + (s2 + s3) + b1[h];
        }
    }
}

// ---------------------------------------------------------------------------
// Kernel 2: pairwise fused readout.  grid(16,8,B) = 512 blocks, block(256).
//   32(i) x 16(j) output tile; thread (tj, ti, hh) computes 4 rows x 1 col
//   partials over its 64-h slice of each 128-h half; 2-way smem reduction.
// ---------------------------------------------------------------------------
#define HS 128          // h per smem-resident half
#define RQ 130          // row stride in floats (130%32==2: conflict-free LDS.64)
#define RQU 65          // row stride in ull

__global__ void __launch_bounds__(256) k_pair(
        const float* __restrict__ W2,
        const float* __restrict__ b2,
        float* __restrict__ out) {
    __shared__ __align__(16) float As[32 * RQ];
    __shared__ __align__(16) float Cs[16 * RQ];
    __shared__ __align__(16) float w2s[H];
    __shared__ __align__(16) float ubs[H];
    __shared__ __align__(16) float psum[128][5];

    int b  = blockIdx.z;
    int i0 = blockIdx.y * 32;
    int j0 = blockIdx.x * 16;
    int tid = threadIdx.x;

    w2s[tid] = W2[tid];
    ubs[tid] = g_ub[b * H + tid];

    int tj = tid & 15;          // col tj (0..15)
    int ti = (tid >> 4) & 7;    // rows ti, ti+8, ti+16, ti+24
    int hh = tid >> 7;          // h-slice within each half (0 or 1)

    ull acc0 = 0, acc1 = 0, acc2 = 0, acc3 = 0;

    #pragma unroll
    for (int half = 0; half < 2; half++) {
        int ho = half * HS;
        __syncthreads();        // (also covers w2s/ubs readiness on half 0)
        // ---- fill As: 32 rows x 32 float4 (ub folded in) ----
        #pragma unroll
        for (int k = 0; k < 4; k++) {
            int idx = tid + k * 256;        // 0..1023: r = idx>>5, q = idx&31
            int r = idx >> 5, q = idx & 31;
            float4 a = ((const float4*)(g_A + ((size_t)(b * N + i0 + r)) * H + ho))[q];
            float4 u = ((const float4*)(ubs + ho))[q];
            float2* da = (float2*)(As + r * RQ + 4 * q);
            da[0] = make_float2(a.x + u.x, a.y + u.y);
            da[1] = make_float2(a.z + u.z, a.w + u.w);
        }
        // ---- fill Cs: 16 rows x 32 float4 ----
        #pragma unroll
        for (int k = 0; k < 2; k++) {
            int idx = tid + k * 256;        // 0..511: r = idx>>5 (0..15)
            int r = idx >> 5, q = idx & 31;
            float4 c = ((const float4*)(g_C + ((size_t)(b * N + j0 + r)) * H + ho))[q];
            float2* dc = (float2*)(Cs + r * RQ + 4 * q);
            dc[0] = make_float2(c.x, c.y);
            dc[1] = make_float2(c.z, c.w);
        }
        __syncthreads();

        // ---- compute: this thread's 32 h-pairs of this half ----
        int hq = hh * 32;                    // ull offset within row
        const ull* a0p = (const ull*)As + (size_t)ti * RQU + hq;
        const ull* a1p = a0p + 8 * RQU;
        const ull* a2p = a0p + 16 * RQU;
        const ull* a3p = a0p + 24 * RQU;
        const ull* cp  = (const ull*)Cs + (size_t)tj * RQU + hq;
        const ull* wp  = (const ull*)(w2s + ho) + hq;

        #pragma unroll 8
        for (int q = 0; q < 32; q++) {
            ull a0 = a0p[q];
            ull a1 = a1p[q];
            ull a2 = a2p[q];
            ull a3 = a3p[q];
            ull c0 = cp[q];
            ull w  = wp[q];
            acc0 = fma2(relu2(add2(a0, c0)), w, acc0);
            acc1 = fma2(relu2(add2(a1, c0)), w, acc1);
            acc2 = fma2(relu2(add2(a2, c0)), w, acc2);
            acc3 = fma2(relu2(add2(a3, c0)), w, acc3);
        }
    }

    // ---- reduce hh halves ----
    float v0 = hsum2(acc0), v1 = hsum2(acc1);
    float v2 = hsum2(acc2), v3 = hsum2(acc3);

    int p = tid & 127;
    if (hh == 1) {
        psum[p][0] = v0; psum[p][1] = v1; psum[p][2] = v2; psum[p][3] = v3;
    }
    __syncthreads();
    if (hh == 0) {
        float b2v = b2[0];
        v0 += psum[p][0]; v1 += psum[p][1]; v2 += psum[p][2]; v3 += psum[p][3];
        size_t base = ((size_t)(b * N)) * N;
        size_t r0 = base + (size_t)(i0 + ti) * N + (j0 + tj);
        out[r0]          = v0 + b2v;
        out[r0 + 8 * N]  = v1 + b2v;
        out[r0 + 16 * N] = v2 + b2v;
        out[r0 + 24 * N] = v3 + b2v;
    }
}

// ---------------------------------------------------------------------------
extern "C" void kernel_launch(void* const* d_in, const int* in_sizes, int n_in,
                              void* d_out, int out_size) {
    const float* x   = (const float*)d_in[0];  // [B,N,F]
    const float* Wp  = (const float*)d_in[1];  // [F,F]
    const float* W1  = (const float*)d_in[2];  // [3F,H]
    const float* b1  = (const float*)d_in[3];  // [H]
    const float* W2  = (const float*)d_in[4];  // [H,1]
    const float* b2  = (const float*)d_in[5];  // [1]
    float* out = (float*)d_out;                // [B,N,N,1]

    k_main<<<132, 256>>>(x, Wp, W1, b1);
    k_pair<<<dim3(N / 16, N / 32, B), 256>>>(W2, b2, out);
}

// round 11
// speedup vs baseline: 1.4118x; 1.0678x over previous
#include <cuda_runtime.h>
#include <cuda_bf16.h>

// Problem constants
#define B 4
#define N 256
#define F 128
#define H 256

typedef unsigned long long ull;

// Scratch (allocation-free rule: __device__ globals)
__device__ __align__(16) float g_meanpart[64][F];  // per-16-row column sums
__device__ __align__(16) float g_ub[B * H];        // u[b,h] + b1[h]
__device__ __align__(16) float g_A[B * N * H];     // relu(x_i) @ W1_i (raw, no ub)
__device__ __align__(16) float g_C[B * N * H];     // relu(x_j) @ W1_j

// ---- packed f32x2 helpers (sm_100+) ---------------------------------------
static __device__ __forceinline__ ull add2(ull a, ull b) {
    ull d; asm("add.rn.f32x2 %0, %1, %2;" : "=l"(d) : "l"(a), "l"(b)); return d;
}
static __device__ __forceinline__ ull fma2(ull a, ull b, ull c) {
    ull d; asm("fma.rn.f32x2 %0, %1, %2, %3;" : "=l"(d) : "l"(a), "l"(b), "l"(c)); return d;
}
static __device__ __forceinline__ ull pack2(float lo, float hi) {
    ull d; asm("mov.b64 %0, {%1, %2};" : "=l"(d) : "f"(lo), "f"(hi)); return d;
}
static __device__ __forceinline__ void unpack2(ull v, float& lo, float& hi) {
    asm("mov.b64 {%0, %1}, %2;" : "=f"(lo), "=f"(hi) : "l"(v));
}
static __device__ __forceinline__ ull relu2(ull v) {
    float lo, hi; unpack2(v, lo, hi);
    return pack2(fmaxf(lo, 0.f), fmaxf(hi, 0.f));
}
static __device__ __forceinline__ float hsum2(ull v) {
    float lo, hi; unpack2(v, lo, hi); return lo + hi;
}

// ---------------------------------------------------------------------------
// Kernel 0: wide column-sum partials.  grid(64), block(256).
//   Block bb: batch b = bb>>4, slice g = bb&15 -> rows [g*16, g*16+16).
//   Thread: f = tid&127, rh = tid>>7 -> 8 rows, 8 independent loads.
// ---------------------------------------------------------------------------
__global__ void __launch_bounds__(256) k_mean(const float* __restrict__ x) {
    __shared__ float part[2][F];
    int bb = blockIdx.x;
    int b = bb >> 4, g = bb & 15;
    int tid = threadIdx.x;
    int f = tid & (F - 1), rh = tid >> 7;

    const float* base = x + ((size_t)(b * N + g * 16 + rh * 8)) * F + f;
    float v0 = base[0 * F], v1 = base[1 * F], v2 = base[2 * F], v3 = base[3 * F];
    float v4 = base[4 * F], v5 = base[5 * F], v6 = base[6 * F], v7 = base[7 * F];
    part[rh][f] = ((v0 + v1) + (v2 + v3)) + ((v4 + v5) + (v6 + v7));
    __syncthreads();
    if (tid < F) g_meanpart[bb][tid] = part[0][tid] + part[1][tid];
}

// ---------------------------------------------------------------------------
// Kernel 1: fused nodegemm (blocks 0..127) + pool-chain (blocks 128..131).
//   256 threads.  Gemm blocks: (row-group of 16 rows) x (h-half of 128).
// ---------------------------------------------------------------------------
#define CF 16         // f per chunk
#define NCHUNK (F / CF)
#define HW 128        // h per gemm block

__global__ void __launch_bounds__(256) k_main(
        const float* __restrict__ x,
        const float* __restrict__ Wp,
        const float* __restrict__ W1,
        const float* __restrict__ b1) {
    __shared__ __align__(16) float rx[F * 16];             // [f][16 rows] 8 KB
    __shared__ __align__(16) float wbuf[2][CF][2][HW];     // 32 KB staged W1a/W1c
    int tid = threadIdx.x;

    if (blockIdx.x < 128) {
        // ================== nodegemm (R5 structure) ==================
        int row0 = (blockIdx.x >> 1) * 16;     // 16 rows per block
        int h0   = (blockIdx.x & 1) * HW;      // h-half
        int hl = tid & (HW - 1);               // 0..127
        int rg = tid >> 7;                     // 0..1 -> rows rg*8..rg*8+7

        // rx packed: word f*16 + r  => row-pairs contiguous (8B)
        #pragma unroll
        for (int k = 0; k < 8; k++) {
            int idx = tid + k * 256;
            int r = idx >> 7, f = idx & (F - 1);
            rx[f * 16 + r] = fmaxf(x[(row0 + r) * F + f], 0.f);
        }

        const float* W1base = W1 + (size_t)F * H + h0;  // rows [F,3F), this h-half

        // prologue: fetch chunk 0 and stage it
        float4 t0, t1, t2, t3;
        {
            #pragma unroll
            for (int k = 0; k < 4; k++) {
                int idx = tid + k * 256;            // 0..1023 float4s
                int part = idx >> 9;                // 0 = A-weights, 1 = C
                int rem = idx & 511;
                int fl = rem >> 5, q = rem & 31;
                float4 v = ((const float4*)(W1base + ((size_t)(part * F + fl)) * H))[q];
                if (k == 0) t0 = v; else if (k == 1) t1 = v;
                else if (k == 2) t2 = v; else t3 = v;
            }
            #pragma unroll
            for (int k = 0; k < 4; k++) {
                int idx = tid + k * 256;
                int part = idx >> 9;
                int rem = idx & 511;
                int fl = rem >> 5, q = rem & 31;
                float4 v = (k == 0) ? t0 : (k == 1) ? t1 : (k == 2) ? t2 : t3;
                ((float4*)&wbuf[0][fl][part][0])[q] = v;
            }
        }
        __syncthreads();

        const ull* rxu = (const ull*)rx;            // [F][8] row-pairs
        ull accA[4] = {0, 0, 0, 0};
        ull accC[4] = {0, 0, 0, 0};

        for (int c = 0; c < NCHUNK; c++) {
            int s = c & 1;
            bool pf = (c + 1) < NCHUNK;
            // prefetch next chunk into registers
            if (pf) {
                int fb = (c + 1) * CF;
                #pragma unroll
                for (int k = 0; k < 4; k++) {
                    int idx = tid + k * 256;
                    int part = idx >> 9;
                    int rem = idx & 511;
                    int fl = rem >> 5, q = rem & 31;
                    float4 v = ((const float4*)(W1base + ((size_t)(part * F + fb + fl)) * H))[q];
                    if (k == 0) t0 = v; else if (k == 1) t1 = v;
                    else if (k == 2) t2 = v; else t3 = v;
                }
            }
            // compute current chunk from smem
            #pragma unroll
            for (int fl = 0; fl < CF; fl++) {
                int f = c * CF + fl;
                float wa = wbuf[s][fl][0][hl];
                float wc = wbuf[s][fl][1][hl];
                ull wa2 = pack2(wa, wa);
                ull wc2 = pack2(wc, wc);
                ull v0 = rxu[f * 8 + rg * 4 + 0];   // broadcast within rg-group
                ull v1 = rxu[f * 8 + rg * 4 + 1];
                ull v2 = rxu[f * 8 + rg * 4 + 2];
                ull v3 = rxu[f * 8 + rg * 4 + 3];
                accA[0] = fma2(v0, wa2, accA[0]);
                accA[1] = fma2(v1, wa2, accA[1]);
                accA[2] = fma2(v2, wa2, accA[2]);
                accA[3] = fma2(v3, wa2, accA[3]);
                accC[0] = fma2(v0, wc2, accC[0]);
                accC[1] = fma2(v1, wc2, accC[1]);
                accC[2] = fma2(v2, wc2, accC[2]);
                accC[3] = fma2(v3, wc2, accC[3]);
            }
            // stage prefetched chunk
            if (pf) {
                int ns = (c + 1) & 1;
                #pragma unroll
                for (int k = 0; k < 4; k++) {
                    int idx = tid + k * 256;
                    int part = idx >> 9;
                    int rem = idx & 511;
                    int fl = rem >> 5, q = rem & 31;
                    float4 v = (k == 0) ? t0 : (k == 1) ? t1 : (k == 2) ? t2 : t3;
                    ((float4*)&wbuf[ns][fl][part][0])[q] = v;
                }
            }
            __syncthreads();
        }

        #pragma unroll
        for (int p = 0; p < 4; p++) {
            int r0g = row0 + rg * 8 + 2 * p;
            float a0, a1, c0, c1;
            unpack2(accA[p], a0, a1);
            unpack2(accC[p], c0, c1);
            g_A[r0g * H + h0 + hl]       = a0;
            g_A[(r0g + 1) * H + h0 + hl] = a1;
            g_C[r0g * H + h0 + hl]       = c0;
            g_C[(r0g + 1) * H + h0 + hl] = c1;
        }
    } else {
        // ================== pool chain (partials precomputed) ==============
        int b = blockIdx.x - 128;
        float* part2 = rx;              // [2][F]
        float* m     = rx + 256;        // [F]
        float* r     = rx + 384;        // [F]

        // Combine 16 column-sum partials -> mean
        {
            int f = tid & (F - 1);
            int g2 = tid >> 7;          // 0..1, 8 partials each
            float s0 = 0.f, s1 = 0.f, s2 = 0.f, s3 = 0.f;
            float s4 = 0.f, s5 = 0.f, s6 = 0.f, s7 = 0.f;
            int pb = b * 16 + g2 * 8;
            s0 = g_meanpart[pb + 0][f];
            s1 = g_meanpart[pb + 1][f];
            s2 = g_meanpart[pb + 2][f];
            s3 = g_meanpart[pb + 3][f];
            s4 = g_meanpart[pb + 4][f];
            s5 = g_meanpart[pb + 5][f];
            s6 = g_meanpart[pb + 6][f];
            s7 = g_meanpart[pb + 7][f];
            part2[g2 * F + f] = ((s0 + s1) + (s2 + s3)) + ((s4 + s5) + (s6 + s7));
        }
        __syncthreads();
        if (tid < F) m[tid] = (part2[tid] + part2[F + tid]) * (1.0f / N);
        __syncthreads();

        // Phase 2: hp[f] = relu(sum m[fin] * Wp[fin, f]).  8 indep accums.
        {
            int f = tid & (F - 1);
            int g = tid >> 7;           // 0..1, 64 fin each
            float s0 = 0.f, s1 = 0.f, s2 = 0.f, s3 = 0.f;
            float s4 = 0.f, s5 = 0.f, s6 = 0.f, s7 = 0.f;
            #pragma unroll
            for (int j = 0; j < 8; j++) {
                int fin = g * 64 + j * 8;
                s0 += m[fin + 0] * Wp[(fin + 0) * F + f];
                s1 += m[fin + 1] * Wp[(fin + 1) * F + f];
                s2 += m[fin + 2] * Wp[(fin + 2) * F + f];
                s3 += m[fin + 3] * Wp[(fin + 3) * F + f];
                s4 += m[fin + 4] * Wp[(fin + 4) * F + f];
                s5 += m[fin + 5] * Wp[(fin + 5) * F + f];
                s6 += m[fin + 6] * Wp[(fin + 6) * F + f];
                s7 += m[fin + 7] * Wp[(fin + 7) * F + f];
            }
            part2[g * F + f] = ((s0 + s1) + (s2 + s3)) + ((s4 + s5) + (s6 + s7));
        }
        __syncthreads();
        if (tid < F) r[tid] = fmaxf(part2[tid] + part2[F + tid], 0.f);
        __syncthreads();

        // Phase 3: u[h] = sum_f r[f] * W1[f, h] + b1[h].  8 indep accums.
        {
            int h = tid;
            float s0 = 0.f, s1 = 0.f, s2 = 0.f, s3 = 0.f;
            float s4 = 0.f, s5 = 0.f, s6 = 0.f, s7 = 0.f;
            #pragma unroll
            for (int j = 0; j < 16; j++) {
                int fb = j * 8;
                s0 += r[fb + 0] * W1[(fb + 0) * H + h];
                s1 += r[fb + 1] * W1[(fb + 1) * H + h];
                s2 += r[fb + 2] * W1[(fb + 2) * H + h];
                s3 += r[fb + 3] * W1[(fb + 3) * H + h];
                s4 += r[fb + 4] * W1[(fb + 4) * H + h];
                s5 += r[fb + 5] * W1[(fb + 5) * H + h];
                s6 += r[fb + 6] * W1[(fb + 6) * H + h];
                s7 += r[fb + 7] * W1[(fb + 7) * H + h];
            }
            g_ub[b * H + h] = ((s0 + s1) + (s2 + s3)) + ((s4 + s5) + (s6 + s7)) + b1[h];
        }
    }
}

// ---------------------------------------------------------------------------
// Kernel 2: pairwise fused readout (R5 verbatim).  grid(8,8,B), block(256)
//   32x32 tile; thread (tj, ti, hh): 4i x 2j partials over its 64-h slice of
//   each 128-h half; 2-way smem reduction combines hh slices.
// ---------------------------------------------------------------------------
#define HS 128          // h per smem-resident half
#define RQ 130          // row stride in floats (130%32==2: conflict-free LDS.64)
#define RQU 65          // row stride in ull

__global__ void __launch_bounds__(256) k_pair(
        const float* __restrict__ W2,
        const float* __restrict__ b2,
        float* __restrict__ out) {
    __shared__ __align__(16) float As[32 * RQ];
    __shared__ __align__(16) float Cs[32 * RQ];
    __shared__ __align__(16) float w2s[H];
    __shared__ __align__(16) float ubs[H];
    __shared__ __align__(16) float psum[128][9];

    int b  = blockIdx.z;
    int i0 = blockIdx.y * 32;
    int j0 = blockIdx.x * 32;
    int tid = threadIdx.x;

    if (tid < 128) {
        w2s[tid] = W2[tid];
        w2s[tid + 128] = W2[tid + 128];
        ubs[tid] = g_ub[b * H + tid];
        ubs[tid + 128] = g_ub[b * H + tid + 128];
    }

    int tj = tid & 15;          // j-group: cols tj, tj+16
    int ti = (tid >> 4) & 7;    // i-group: rows ti, ti+8, ti+16, ti+24
    int hh = tid >> 7;          // h-slice within each half (0 or 1)

    ull acc00 = 0, acc01 = 0;   // row ti
    ull acc10 = 0, acc11 = 0;   // row ti+8
    ull acc20 = 0, acc21 = 0;   // row ti+16
    ull acc30 = 0, acc31 = 0;   // row ti+24

    #pragma unroll
    for (int half = 0; half < 2; half++) {
        int ho = half * HS;
        __syncthreads();        // (also covers w2s/ubs readiness on half 0)
        // ---- fill tiles (ub folded into A); 256 threads, 4+4 float4 each ----
        #pragma unroll
        for (int k = 0; k < 4; k++) {
            int idx = tid + k * 256;        // 0..1023: r = idx>>5, q = idx&31
            int r = idx >> 5, q = idx & 31;
            float4 a = ((const float4*)(g_A + ((size_t)(b * N + i0 + r)) * H + ho))[q];
            float4 u = ((const float4*)(ubs + ho))[q];
            float2* da = (float2*)(As + r * RQ + 4 * q);
            da[0] = make_float2(a.x + u.x, a.y + u.y);
            da[1] = make_float2(a.z + u.z, a.w + u.w);
            float4 c = ((const float4*)(g_C + ((size_t)(b * N + j0 + r)) * H + ho))[q];
            float2* dc = (float2*)(Cs + r * RQ + 4 * q);
            dc[0] = make_float2(c.x, c.y);
            dc[1] = make_float2(c.z, c.w);
        }
        __syncthreads();

        // ---- compute: this thread's 32 h-pairs of this half ----
        int hq = hh * 32;                    // ull offset within row
        const ull* a0p = (const ull*)As + (size_t)ti * RQU + hq;
        const ull* a1p = a0p + 8 * RQU;
        const ull* a2p = a0p + 16 * RQU;
        const ull* a3p = a0p + 24 * RQU;
        const ull* c0p = (const ull*)Cs + (size_t)tj * RQU + hq;
        const ull* c1p = c0p + 16 * RQU;
        const ull* wp  = (const ull*)(w2s + ho) + hq;

        #pragma unroll 8
        for (int q = 0; q < 32; q++) {
            ull a0 = a0p[q];
            ull a1 = a1p[q];
            ull a2 = a2p[q];
            ull a3 = a3p[q];
            ull c0 = c0p[q];
            ull c1 = c1p[q];
            ull w  = wp[q];
            acc00 = fma2(relu2(add2(a0, c0)), w, acc00);
            acc01 = fma2(relu2(add2(a0, c1)), w, acc01);
            acc10 = fma2(relu2(add2(a1, c0)), w, acc10);
            acc11 = fma2(relu2(add2(a1, c1)), w, acc11);
            acc20 = fma2(relu2(add2(a2, c0)), w, acc20);
            acc21 = fma2(relu2(add2(a2, c1)), w, acc21);
            acc30 = fma2(relu2(add2(a3, c0)), w, acc30);
            acc31 = fma2(relu2(add2(a3, c1)), w, acc31);
        }
    }

    // ---- reduce hh halves ----
    float v0 = hsum2(acc00), v1 = hsum2(acc01);
    float v2 = hsum2(acc10), v3 = hsum2(acc11);
    float v4 = hsum2(acc20), v5 = hsum2(acc21);
    float v6 = hsum2(acc30), v7 = hsum2(acc31);

    int p = tid & 127;
    if (hh == 1) {
        psum[p][0] = v0; psum[p][1] = v1; psum[p][2] = v2; psum[p][3] = v3;
        psum[p][4] = v4; psum[p][5] = v5; psum[p][6] = v6; psum[p][7] = v7;
    }
    __syncthreads();
    if (hh == 0) {
        float b2v = b2[0];
        v0 += psum[p][0]; v1 += psum[p][1]; v2 += psum[p][2]; v3 += psum[p][3];
        v4 += psum[p][4]; v5 += psum[p][5]; v6 += psum[p][6]; v7 += psum[p][7];
        size_t base = ((size_t)(b * N)) * N;
        size_t r0 = base + (size_t)(i0 + ti) * N + j0;
        out[r0 + tj]               = v0 + b2v;
        out[r0 + tj + 16]          = v1 + b2v;
        out[r0 + 8 * N + tj]       = v2 + b2v;
        out[r0 + 8 * N + tj + 16]  = v3 + b2v;
        out[r0 + 16 * N + tj]      = v4 + b2v;
        out[r0 + 16 * N + tj + 16] = v5 + b2v;
        out[r0 + 24 * N + tj]      = v6 + b2v;
        out[r0 + 24 * N + tj + 16] = v7 + b2v;
    }
}

// ---------------------------------------------------------------------------
extern "C" void kernel_launch(void* const* d_in, const int* in_sizes, int n_in,
                              void* d_out, int out_size) {
    const float* x   = (const float*)d_in[0];  // [B,N,F]
    const float* Wp  = (const float*)d_in[1];  // [F,F]
    const float* W1  = (const float*)d_in[2];  // [3F,H]
    const float* b1  = (const float*)d_in[3];  // [H]
    const float* W2  = (const float*)d_in[4];  // [H,1]
    const float* b2  = (const float*)d_in[5];  // [1]
    float* out = (float*)d_out;                // [B,N,N,1]

    k_mean<<<64, 256>>>(x);
    k_main<<<132, 256>>>(x, Wp, W1, b1);
    k_pair<<<dim3(N / 32, N / 32, B), 256>>>(W2, b2, out);
}